// round 17
// baseline (speedup 1.0000x reference)
#include <cuda_runtime.h>
#include <math.h>

// Problem constants (fixed by reference)
#define T_STEPS 128
#define MATPTS  16
#define PPT     2                    // material points per thread (1 packed pair)
#define TPB     (MATPTS / PPT)       // threads per batch element = 8
#define BLOCK   128

// Material constants, derived in double precision at compile time
static constexpr double E_MOD_D = 3130.0;
static constexpr double NU_D    = 0.37;
static constexpr double MU_D    = E_MOD_D / (2.0 * (1.0 + NU_D));
static constexpr double LAM_D   = E_MOD_D * NU_D / ((1.0 + NU_D) * (1.0 - 2.0 * NU_D));
static constexpr double SIGY_D  = 64.8;
static constexpr double H_D     = 300.0;
static constexpr double KINV_D  = 1.0 / (3.0 * MU_D + H_D);
static constexpr double SQRT3_D = 1.7320508075688772;

static constexpr float TWO_MU_F = (float)(2.0 * MU_D);
static constexpr float K3_F     = (float)(LAM_D + 2.0 * MU_D / 3.0);  // pm = K3*(e0+e1)
static constexpr float NC23_F   = (float)(-2.0 * MU_D / 3.0);         // deviator correction
static constexpr float KS3_F    = (float)(SQRT3_D * KINV_D);          // Kinv*sqrt(3)
static constexpr float NHK_F    = (float)(-H_D * KINV_D);             // -H*Kinv
static constexpr float NYS0_F   = (float)(-SIGY_D * KINV_D);          // initial yield state
static constexpr float N15S3_F  = (float)(-1.5 / SQRT3_D);            // -1.5/sqrt(3)

// ---- packed fp32x2 helpers (sm_100+ only) ---------------------------------
typedef unsigned long long u64t;
struct F2 { u64t v; };

__device__ __forceinline__ F2 f2pack(float lo, float hi) {
    F2 r; asm("mov.b64 %0, {%1, %2};" : "=l"(r.v) : "f"(lo), "f"(hi)); return r;
}
__device__ __forceinline__ void f2unpack(F2 a, float& lo, float& hi) {
    asm("mov.b64 {%0, %1}, %2;" : "=f"(lo), "=f"(hi) : "l"(a.v));
}
__device__ __forceinline__ F2 f2fma(F2 a, F2 b, F2 c) {
    F2 r; asm("fma.rn.f32x2 %0, %1, %2, %3;" : "=l"(r.v) : "l"(a.v), "l"(b.v), "l"(c.v)); return r;
}
__device__ __forceinline__ F2 f2add(F2 a, F2 b) {
    F2 r; asm("add.rn.f32x2 %0, %1, %2;" : "=l"(r.v) : "l"(a.v), "l"(b.v)); return r;
}
__device__ __forceinline__ F2 f2mul(F2 a, F2 b) {
    F2 r; asm("mul.rn.f32x2 %0, %1, %2;" : "=l"(r.v) : "l"(a.v), "l"(b.v)); return r;
}
__device__ __forceinline__ F2 f2relu(F2 a) {
    float lo, hi; f2unpack(a, lo, hi);
    return f2pack(fmaxf(lo, 0.0f), fmaxf(hi, 0.0f));
}
__device__ __forceinline__ F2 f2zero() { F2 r; r.v = 0ULL; return r; }

__global__ void __launch_bounds__(BLOCK, 6)
prnn_j2_kernel(const float* __restrict__ x,
               const float* __restrict__ W1,
               const float* __restrict__ W2,
               float* __restrict__ out,
               int B)
{
    const int tid = blockIdx.x * BLOCK + threadIdx.x;
    const int b   = tid >> 3;           // batch element
    const int sub = tid & 7;            // sub-lane within the 8-thread group
    if (b >= B) return;

    // loop-invariant predicates / routing for the transpose-reduction
    const bool lo4 = (sub < 4);
    const bool lo2 = (sub < 2);
    const bool mid = (sub < 4) && (sub >= 2);
    const bool r2sel = ((sub & 2) != 0);
    const bool do_store = ((sub & 1) == 0) && (sub < 6);
    const int  comp = sub >> 1;

    // ---- Packed per-thread weight slices --------------------------------
    // W1 row 2 (shear) pre-scaled by 0.5 so eexy = e2' + npxy.
    const int mlo = sub * PPT;
    F2 w1p[3][3];
    F2 w2p[3][3];
    #pragma unroll
    for (int j = 0; j < 3; ++j) {
        const float sc = (j == 2) ? 0.5f : 1.0f;
        #pragma unroll
        for (int f = 0; f < 3; ++f)
            w1p[j][f] = f2pack(sc * __ldg(&W1[(3 * mlo + j) * 3 + f]),
                               sc * __ldg(&W1[(3 * (mlo + 1) + j) * 3 + f]));
    }
    #pragma unroll
    for (int o = 0; o < 3; ++o)
        #pragma unroll
        for (int j = 0; j < 3; ++j) {
            float wl = __ldg(&W2[o * 48 + 3 * mlo + j]);
            float wh = __ldg(&W2[o * 48 + 3 * (mlo + 1) + j]);
            w2p[o][j] = f2pack(log1pf(expf(wl)), log1pf(expf(wh)));
        }

    // ---- Packed constants --------------------------------------------------
    const F2 TWOMU2 = f2pack(TWO_MU_F, TWO_MU_F);
    const F2 K32    = f2pack(K3_F,     K3_F);
    const F2 NC232  = f2pack(NC23_F,   NC23_F);
    const F2 KS32   = f2pack(KS3_F,    KS3_F);
    const F2 NHK2   = f2pack(NHK_F,    NHK_F);
    const F2 N15S32 = f2pack(N15S3_F,  N15S3_F);
    const F2 ONE2   = f2pack(1.0f,     1.0f);
    const F2 TINY2  = f2pack(1e-24f,   1e-24f);

    // ---- Committed history (negated plastic strain; folded yield state) --
    F2 npxx = f2zero(), npyy = f2zero(), npxy = f2zero();
    F2 nysK = f2pack(NYS0_F, NYS0_F);   // Kinv*(-sigy - H*alpha)

    const float2* xq = (const float2*)(x + (size_t)b * (T_STEPS * 3));
    float*        opc = out + (size_t)b * (T_STEPS * 3) + comp;

    // J2 update + fc2 partials (reduction is lagged, done separately)
    auto math = [&](float ex, float ey, float eg, float& r0, float& r1, float& r2) {
        const F2 ex2 = f2pack(ex, ex);
        const F2 ey2 = f2pack(ey, ey);
        const F2 eg2 = f2pack(eg, eg);

        // fc1: per-point strain (row 2 pre-scaled by 0.5)
        const F2 e0 = f2fma(ex2, w1p[0][0], f2fma(ey2, w1p[0][1], f2mul(eg2, w1p[0][2])));
        const F2 e1 = f2fma(ex2, w1p[1][0], f2fma(ey2, w1p[1][1], f2mul(eg2, w1p[1][2])));
        const F2 e2 = f2fma(ex2, w1p[2][0], f2fma(ey2, w1p[2][1], f2mul(eg2, w1p[2][2])));

        // elastic predictor, deviatoric form (state negated)
        const F2 eexx = f2add(e0, npxx);
        const F2 eeyy = f2add(e1, npyy);
        const F2 eexy = f2add(e2, npxy);
        const F2 t01  = f2add(e0, e1);
        const F2 pm   = f2mul(K32,  t01);
        const F2 nctr = f2mul(NC232, t01);
        const F2 dxx  = f2fma(TWOMU2, eexx, nctr);
        const F2 dyy  = f2fma(TWOMU2, eeyy, nctr);
        const F2 sxy  = f2mul(TWOMU2, eexy);

        // u = dxx^2 + dxx*dyy + dyy^2 + sxy^2 (q^2 = 3u); TINY seed guards u=0
        const F2 sd  = f2add(dxx, dyy);
        const F2 A   = f2fma(sxy, sxy, TINY2);
        const F2 p1  = f2mul(dxx, sd);
        const F2 p2  = f2fma(dyy, dyy, A);
        const F2 u2  = f2add(p1, p2);

        // radial return (sqrt(3), Kinv folded); only rsqrt is scalar
        float u_lo, u_hi;
        f2unpack(u2, u_lo, u_hi);
        const F2 r2p = f2pack(rsqrtf(u_lo), rsqrtf(u_hi));
        const F2 nr2 = f2mul(N15S32, r2p);
        const F2 ur2 = f2mul(u2, r2p);             // sqrt(u) = q/sqrt(3)
        const F2 fk2 = f2fma(KS32, ur2, nysK);     // Kinv*(q - sigy - H*alpha)
        const F2 dg2 = f2relu(fk2);
        nysK = f2fma(NHK2, dg2, nysK);
        const F2 nc2 = f2mul(dg2, nr2);            // -1.5*dgam/q

        // commit plastic strain
        npxx = f2fma(nc2, dxx, npxx);
        npyy = f2fma(nc2, dyy, npyy);
        npxy = f2fma(nc2, sxy, npxy);

        // corrected stress: o = d*(1 + 2mu*nc) + pm
        const F2 wf  = f2fma(TWOMU2, nc2, ONE2);
        const F2 oxx = f2fma(dxx, wf, pm);
        const F2 oyy = f2fma(dyy, wf, pm);
        const F2 oxy = f2mul(sxy, wf);

        // fc2 partial (softplus weights)
        const F2 a0 = f2fma(oxx, w2p[0][0], f2fma(oyy, w2p[0][1], f2mul(oxy, w2p[0][2])));
        const F2 a1 = f2fma(oxx, w2p[1][0], f2fma(oyy, w2p[1][1], f2mul(oxy, w2p[1][2])));
        const F2 a2 = f2fma(oxx, w2p[2][0], f2fma(oyy, w2p[2][1], f2mul(oxy, w2p[2][2])));

        float a0l, a0h, a1l, a1h, a2l, a2h;
        f2unpack(a0, a0l, a0h);
        f2unpack(a1, a1l, a1h);
        f2unpack(a2, a2l, a2h);
        r0 = a0l + a0h; r1 = a1l + a1h; r2 = a2l + a2h;
    };

    // lagged transpose-reduction + store (4 SHFL); runs one step behind math
    auto reduce_store = [&](float r0, float r1, float r2, int t, bool en) {
        float v1 = lo4 ? r2 : r0;
        float w1 = __shfl_xor_sync(0xffffffffu, v1, 4);
        if (lo4) r0 += w1; else r2 += w1;
        float w2 = __shfl_xor_sync(0xffffffffu, r1, 4);
        if (lo4) r1 += w2;
        float v3 = lo4 ? (r2sel ? r0 : r1) : r2;
        float w3 = __shfl_xor_sync(0xffffffffu, v3, 2);
        if (lo2)      r0 += w3;
        else if (mid) r1 += w3;
        else          r2 += w3;
        float v4 = lo2 ? r0 : (lo4 ? r1 : r2);
        float w4 = __shfl_xor_sync(0xffffffffu, v4, 1);
        const float total = v4 + w4;
        if (do_store && en) opc[3 * t] = total;
    };

    // 4-step unrolled main loop with rotating lagged partials.
    // x loads at iteration top; their latency is covered by the lagged
    // reduction of the previous step.
    float p0 = 0.f, p1 = 0.f, p2 = 0.f;   // partials of step 4k-1

    #pragma unroll 1
    for (int k = 0; k < T_STEPS / 4; ++k) {
        const float2 cA = xq[0], cB = xq[1], cC = xq[2];
        const float2 cD = xq[3], cE = xq[4], cF = xq[5];

        float u0, u1, u2, v0, v1, v2;

        math(cA.x, cA.y, cB.x, u0, u1, u2);          // step 4k
        reduce_store(p0, p1, p2, 4 * k - 1, k > 0);  // step 4k-1

        math(cB.y, cC.x, cC.y, v0, v1, v2);          // step 4k+1
        reduce_store(u0, u1, u2, 4 * k, true);       // step 4k

        math(cD.x, cD.y, cE.x, u0, u1, u2);          // step 4k+2
        reduce_store(v0, v1, v2, 4 * k + 1, true);   // step 4k+1

        math(cE.y, cF.x, cF.y, v0, v1, v2);          // step 4k+3
        reduce_store(u0, u1, u2, 4 * k + 2, true);   // step 4k+2

        p0 = v0; p1 = v1; p2 = v2;
        xq += 6;
    }
    // drain: final step's reduction
    reduce_store(p0, p1, p2, T_STEPS - 1, true);
}

extern "C" void kernel_launch(void* const* d_in, const int* in_sizes, int n_in,
                              void* d_out, int out_size)
{
    const float* x  = (const float*)d_in[0];   // [B, T, 3]
    const float* W1 = (const float*)d_in[1];   // [48, 3]
    const float* W2 = (const float*)d_in[2];   // [3, 48]
    float* out      = (float*)d_out;           // [B, T, 3]

    const int B = in_sizes[0] / (T_STEPS * 3);
    const int total_threads = B * TPB;
    const int grid = (total_threads + BLOCK - 1) / BLOCK;

    prnn_j2_kernel<<<grid, BLOCK>>>(x, W1, W2, out, B);
}